// round 4
// baseline (speedup 1.0000x reference)
#include <cuda_runtime.h>

// PAU rational activation: out = P(z)/Q(z), z = x + center.
// x: [16,2048,4096] f32 (N = 134217728), center[1], numerator[6], denominator[4].
// Strictly HBM/LTS-bound: 1 GiB traffic, measured at ~98% of L2 fabric cap.
// This round: MLP_p1=8 (32 elems/thread), 16384 blocks -> fewer waves.

struct PauParams {
    float c;
    float a0, a1, a2, a3, a4, a5;
    float b0, b1, b2, b3;   // already |.|'d at load time
};

__device__ __forceinline__ float pau_one(float x, const PauParams& P) {
    float z = x + P.c;
    float p = P.a5;
    p = fmaf(p, z, P.a4);
    p = fmaf(p, z, P.a3);
    p = fmaf(p, z, P.a2);
    p = fmaf(p, z, P.a1);
    p = fmaf(p, z, P.a0);
    float az = fabsf(z);
    float q = P.b3;
    q = fmaf(q, az, P.b2);
    q = fmaf(q, az, P.b1);
    q = fmaf(q, az, P.b0);
    q = fmaf(q, az, 1.0f);
    // fast division: MUFU.RCP + FMUL, err ~2^-21 << 1e-3 tolerance
    return __fdividef(p, q);
}

__device__ __forceinline__ float4 pau_vec(float4 v, const PauParams& P) {
    float4 r;
    r.x = pau_one(v.x, P);
    r.y = pau_one(v.y, P);
    r.z = pau_one(v.z, P);
    r.w = pau_one(v.w, P);
    return r;
}

__device__ __forceinline__ PauParams load_params(
    const float* __restrict__ center,
    const float* __restrict__ num,
    const float* __restrict__ den) {
    PauParams P;
    P.c  = __ldg(center);
    P.a0 = __ldg(num + 0); P.a1 = __ldg(num + 1); P.a2 = __ldg(num + 2);
    P.a3 = __ldg(num + 3); P.a4 = __ldg(num + 4); P.a5 = __ldg(num + 5);
    P.b0 = fabsf(__ldg(den + 0)); P.b1 = fabsf(__ldg(den + 1));
    P.b2 = fabsf(__ldg(den + 2)); P.b3 = fabsf(__ldg(den + 3));
    return P;
}

// Main kernel: 256 threads/block, each thread processes 8 float4 (32 elems),
// all 8 loads front-batched (MLP_p1=8). Block covers 2048 consecutive float4s.
__global__ void __launch_bounds__(256) pau_kernel32(
    const float4* __restrict__ x4, float4* __restrict__ o4,
    const float* __restrict__ center,
    const float* __restrict__ num,
    const float* __restrict__ den) {
    const PauParams P = load_params(center, num, den);

    unsigned base = blockIdx.x * 2048u + threadIdx.x;

    float4 v[8];
#pragma unroll
    for (int j = 0; j < 8; j++)
        v[j] = __ldcs(x4 + base + (unsigned)j * 256u);

#pragma unroll
    for (int j = 0; j < 8; j++)
        __stcs(o4 + base + (unsigned)j * 256u, pau_vec(v[j], P));
}

// Generic tail kernel for leftover elements (unused for this exact shape).
__global__ void pau_tail(const float* __restrict__ x, float* __restrict__ out,
                         const float* __restrict__ center,
                         const float* __restrict__ num,
                         const float* __restrict__ den,
                         long long start, long long n) {
    const PauParams P = load_params(center, num, den);
    long long i = start + (long long)blockIdx.x * blockDim.x + threadIdx.x;
    if (i < n) out[i] = pau_one(x[i], P);
}

extern "C" void kernel_launch(void* const* d_in, const int* in_sizes, int n_in,
                              void* d_out, int out_size) {
    const float* x = (const float*)d_in[0];
    const float* center = (const float*)d_in[1];
    const float* numerator = (const float*)d_in[2];
    const float* denominator = (const float*)d_in[3];
    float* out = (float*)d_out;

    long long n = (long long)in_sizes[0];
    long long n4 = n / 4;
    long long nblocks = n4 / 2048;       // each block covers 8192 elements
    long long covered = nblocks * 8192;

    if (nblocks > 0) {
        pau_kernel32<<<(unsigned)nblocks, 256>>>(
            (const float4*)x, (float4*)out, center, numerator, denominator);
    }
    if (covered < n) {
        long long rem = n - covered;
        int tb = (int)((rem + 255) / 256);
        pau_tail<<<tb, 256>>>(x, out, center, numerator, denominator, covered, n);
    }
}